// round 10
// baseline (speedup 1.0000x reference)
#include <cuda_runtime.h>
#include <cuda_fp16.h>

// GCN symmetric-normalized CSR aggregation, two-phase:
//   Phase 1: norm_feat[s,:] = (half) rsqrt(deg[s]) * feat[s,:]; plus a
//            guaranteed all-zero row at index MAX_NODES (padding target).
//   Phase 2: out[d,:] = rsqrt(deg[d]) * sum_{e in row d} norm_feat[col[e],:]
//
// Phase 2: one warp per PAIR of adjacent destination nodes (2w, 2w+1) —
// two independent gather chains interleave so L2-latency stalls overlap.
// 16 lanes cover a 128B fp16 row (8B/lane); each LDG.64 gathers two edges
// (one per half-warp). Offsets staged deinterleaved in smem; invalid slots
// point at the zero row -> branch-free inner loop with 8 LDG.64 in flight.
// Four edges folded per 2-level HADD2 tree, fp32 accumulation.

#define FEAT 64
#define ROW_BYTES (FEAT * 2)     // 128B per fp16 feature row
#define WARPS_PER_BLOCK 4
#define THREADS (WARPS_PER_BLOCK * 32)
#define FULL 0xffffffffu

#define MAX_NODES 100000
// +1 row of zeros used as the padding gather target.
__device__ __half g_norm_feat[(size_t)(MAX_NODES + 1) * FEAT];

__global__ __launch_bounds__(256) void scale_feat_kernel(
    const float* __restrict__ node_feat,
    const float* __restrict__ degrees,
    int n_nodes)
{
    const int i = blockIdx.x * blockDim.x + threadIdx.x;   // float4 index
    const int total = (n_nodes + 1) * (FEAT / 4);          // +1: zero row
    if (i >= total) return;
    const int node = i >> 4;                               // 16 float4 per node
    __half2 h0, h1;
    if (node < n_nodes) {
        const float nd = rsqrtf(__ldg(&degrees[node]));
        float4 v = __ldg((const float4*)node_feat + i);
        h0 = __floats2half2_rn(v.x * nd, v.y * nd);
        h1 = __floats2half2_rn(v.z * nd, v.w * nd);
    } else {
        h0 = __floats2half2_rn(0.f, 0.f);
        h1 = h0;
    }
    __half2* dst = (__half2*)g_norm_feat + (size_t)i * 2;
    dst[0] = h0;
    dst[1] = h1;
}

__global__ __launch_bounds__(THREADS) void gcn_agg_kernel(
    const int* __restrict__ row_ptr,
    const int* __restrict__ col_idx,
    const float* __restrict__ degrees,
    float* __restrict__ out,
    int n_nodes)
{
    __shared__ __align__(16) unsigned sm_off[WARPS_PER_BLOCK][64];

    const int wslot = threadIdx.x >> 5;
    const int pair  = blockIdx.x * WARPS_PER_BLOCK + wslot;
    const int lane  = threadIdx.x & 31;

    const int d0 = 2 * pair;
    if (d0 >= n_nodes) return;
    const int d1 = d0 + 1;
    const bool valid1 = (d1 < n_nodes);

    const int half = lane >> 4;          // which edge of the LDG.64 pair
    const int fl   = lane & 15;          // 8B slot within the 128B row

    const int e0 = __ldg(&row_ptr[d0]);
    const int e1 = __ldg(&row_ptr[d1]);           // row_ptr has n_nodes+1 entries
    const int e2 = valid1 ? __ldg(&row_ptr[d1 + 1]) : e1;
    const int deg0 = e1 - e0;
    const int deg1 = e2 - e1;
    const int maxdeg = max(deg0, deg1);

    const char* __restrict__ base = (const char*)g_norm_feat + (size_t)fl * 8;
    const unsigned ZOFF = (unsigned)MAX_NODES * ROW_BYTES;   // zero-row offset

    float2 a0 = make_float2(0.f, 0.f);   // node d0 accumulators
    float2 a1 = make_float2(0.f, 0.f);
    float2 b0 = make_float2(0.f, 0.f);   // node d1 accumulators
    float2 b1 = make_float2(0.f, 0.f);

    const unsigned* __restrict__ my0 = &sm_off[wslot][half << 4];
    const unsigned* __restrict__ my1 = my0 + 32;

    for (int bb = 0; bb < maxdeg; bb += 32) {
        const int mye = bb + lane;
        unsigned o0 = ZOFF, o1 = ZOFF;
        if (mye < deg0) o0 = (unsigned)__ldg(&col_idx[e0 + mye]) * ROW_BYTES;
        if (mye < deg1) o1 = (unsigned)__ldg(&col_idx[e1 + mye]) * ROW_BYTES;
        const int slot = ((lane & 1) << 4) | (lane >> 1);    // deinterleave
        sm_off[wslot][slot]      = o0;
        sm_off[wslot][32 + slot] = o1;
        __syncwarp();

        const int cm = min(32, maxdeg - bb);
        const int iters = (((cm + 1) >> 1) + 3) >> 2;   // 4 edges/half/iter

        for (int it = 0; it < iters; ++it) {
            const uint4 oa = *(const uint4*)(my0 + (it << 2));
            const uint4 ob = *(const uint4*)(my1 + (it << 2));

            const uint2 x0 = __ldg((const uint2*)(base + oa.x));
            const uint2 x1 = __ldg((const uint2*)(base + oa.y));
            const uint2 x2 = __ldg((const uint2*)(base + oa.z));
            const uint2 x3 = __ldg((const uint2*)(base + oa.w));
            const uint2 y0 = __ldg((const uint2*)(base + ob.x));
            const uint2 y1 = __ldg((const uint2*)(base + ob.y));
            const uint2 y2 = __ldg((const uint2*)(base + ob.z));
            const uint2 y3 = __ldg((const uint2*)(base + ob.w));

            // node d0: 2-level fp16 tree over 4 edges, per half2 slot
            {
                const __half2 t0 = __hadd2(*(const __half2*)&x0.x, *(const __half2*)&x1.x);
                const __half2 t1 = __hadd2(*(const __half2*)&x2.x, *(const __half2*)&x3.x);
                const float2 f0 = __half22float2(__hadd2(t0, t1));
                const __half2 s0 = __hadd2(*(const __half2*)&x0.y, *(const __half2*)&x1.y);
                const __half2 s1 = __hadd2(*(const __half2*)&x2.y, *(const __half2*)&x3.y);
                const float2 f1 = __half22float2(__hadd2(s0, s1));
                a0.x += f0.x; a0.y += f0.y;
                a1.x += f1.x; a1.y += f1.y;
            }
            // node d1
            {
                const __half2 t0 = __hadd2(*(const __half2*)&y0.x, *(const __half2*)&y1.x);
                const __half2 t1 = __hadd2(*(const __half2*)&y2.x, *(const __half2*)&y3.x);
                const float2 f0 = __half22float2(__hadd2(t0, t1));
                const __half2 s0 = __hadd2(*(const __half2*)&y0.y, *(const __half2*)&y1.y);
                const __half2 s1 = __hadd2(*(const __half2*)&y2.y, *(const __half2*)&y3.y);
                const float2 f1 = __half22float2(__hadd2(s0, s1));
                b0.x += f0.x; b0.y += f0.y;
                b1.x += f1.x; b1.y += f1.y;
            }
        }
        __syncwarp();
    }

    // Fold the two half-warps (lanes with equal fl share feature slots).
    a0.x += __shfl_xor_sync(FULL, a0.x, 16);
    a0.y += __shfl_xor_sync(FULL, a0.y, 16);
    a1.x += __shfl_xor_sync(FULL, a1.x, 16);
    a1.y += __shfl_xor_sync(FULL, a1.y, 16);
    b0.x += __shfl_xor_sync(FULL, b0.x, 16);
    b0.y += __shfl_xor_sync(FULL, b0.y, 16);
    b1.x += __shfl_xor_sync(FULL, b1.x, 16);
    b1.y += __shfl_xor_sync(FULL, b1.y, 16);

    // Half 0 stores node d0's row, half 1 stores node d1's row: one warp-wide
    // STG.128 covering 512B (two coalesced 256B rows).
    const int dn = half ? d1 : d0;
    const float nd = rsqrtf(__ldg(&degrees[half ? (valid1 ? d1 : d0) : d0]));
    const float2 s0 = half ? b0 : a0;
    const float2 s1 = half ? b1 : a1;
    float4 r;
    r.x = s0.x * nd;
    r.y = s0.y * nd;
    r.z = s1.x * nd;
    r.w = s1.y * nd;
    if (!half || valid1)
        ((float4*)out)[(size_t)dn * (FEAT / 4) + fl] = r;
}

// Full-precision fallback for n_nodes > MAX_NODES.
__global__ __launch_bounds__(THREADS) void gcn_agg_fallback(
    const int* __restrict__ row_ptr,
    const int* __restrict__ col_idx,
    const float* __restrict__ node_feat,
    const float* __restrict__ degrees,
    float* __restrict__ out,
    int n_nodes)
{
    const int warp_id = blockIdx.x * WARPS_PER_BLOCK + (threadIdx.x >> 5);
    const int lane = threadIdx.x & 31;
    if (warp_id >= n_nodes) return;

    const int start = __ldg(&row_ptr[warp_id]);
    const int end   = __ldg(&row_ptr[warp_id + 1]);
    float2 acc = make_float2(0.f, 0.f);
    const float2* nf = (const float2*)node_feat;
    for (int e = start; e < end; ++e) {
        const int s = __ldg(&col_idx[e]);
        const float ns = rsqrtf(__ldg(&degrees[s]));
        const float2 v = __ldg(nf + (size_t)s * (FEAT / 2) + lane);
        acc.x = fmaf(ns, v.x, acc.x);
        acc.y = fmaf(ns, v.y, acc.y);
    }
    const float nd = rsqrtf(__ldg(&degrees[warp_id]));
    float2 r; r.x = acc.x * nd; r.y = acc.y * nd;
    ((float2*)out)[(size_t)warp_id * (FEAT / 2) + lane] = r;
}

extern "C" void kernel_launch(void* const* d_in, const int* in_sizes, int n_in,
                              void* d_out, int out_size)
{
    const int*   row_ptr   = (const int*)d_in[0];
    const int*   col_idx   = (const int*)d_in[1];
    const float* node_feat = (const float*)d_in[2];
    const float* degrees   = (const float*)d_in[3];
    float* out = (float*)d_out;

    const int n_nodes = in_sizes[0] - 1;

    if (n_nodes <= MAX_NODES) {
        const int total4 = (n_nodes + 1) * (FEAT / 4);
        scale_feat_kernel<<<(total4 + 255) / 256, 256>>>(node_feat, degrees, n_nodes);
        const int pairs = (n_nodes + 1) / 2;
        const int blocks = (pairs + WARPS_PER_BLOCK - 1) / WARPS_PER_BLOCK;
        gcn_agg_kernel<<<blocks, THREADS>>>(row_ptr, col_idx, degrees, out, n_nodes);
    } else {
        const int blocks = (n_nodes + WARPS_PER_BLOCK - 1) / WARPS_PER_BLOCK;
        gcn_agg_fallback<<<blocks, THREADS>>>(row_ptr, col_idx, node_feat,
                                              degrees, out, n_nodes);
    }
}